// round 15
// baseline (speedup 1.0000x reference)
#include <cuda_runtime.h>
#include <cuda_bf16.h>
#include <math.h>

#define BB 1024
#define SS 256
#define DD 128
#define HH 512
#define GG 2048
#define KPA 640          // A: 10 chunks (x_c 2 + hdec 8)
#define KPW 768          // W: 12 chunks
#define NCH 12
#define NIMP (1024*256*128)

#define TILE_A 8192                   // 64 rows x 128B
#define TILE_W 16384                  // 128 rows x 128B
#define BUF_B (2*TILE_A + 2*TILE_W)   // 49152
#define GATES_SMEM (2*BUF_B + 32 + 256)

// mid dynamic smem layout (floats)
#define MID_H    0
#define MID_HD   (8*516)
#define MID_BS   (2*8*516)
#define MID_RED  (MID_BS + 2*16*132)
#define MID_D    (MID_RED + 256)
#define MID_SMEM ((MID_D + 8)*4)

typedef unsigned long long ull;
typedef unsigned int uint;

__device__ uint4 g_AhV[BB*KPA/8];
__device__ uint4 g_AlV[BB*KPA/8];
__device__ uint4 g_WhV[(size_t)GG*KPW/8];
__device__ uint4 g_WlV[(size_t)GG*KPW/8];
__device__ uint4 g_MsV[(size_t)SS*2*BB*64/8];
__device__ float g_XF[(size_t)BB*SS*DD];
__device__ float g_h[HH*BB];          // [j][b]
__device__ float g_c[HH*BB];          // [j][b]
__device__ float g_Bc[HH*DD];         // WhrT [k][n]
__device__ float g_Bc2[DD*DD];        // WfrT [k][n]
__device__ float g_biasI[GG];
__device__ float g_Wd[GG];
__device__ float g_loss[SS];
__device__ float g_msum[SS];

#define g_Ah ((__nv_bfloat16*)g_AhV)
#define g_Al ((__nv_bfloat16*)g_AlV)
#define g_Wh ((__nv_bfloat16*)g_WhV)
#define g_Wl ((__nv_bfloat16*)g_WlV)
#define g_Ms ((__nv_bfloat16*)g_MsV)

__device__ __forceinline__ size_t aoff(int b, int k){
    int ch = k >> 6;
    int u  = ((k >> 3) & 7) ^ (b & 7);
    return (((size_t)ch*BB + b)*8 + u)*8 + (k & 7);
}
__device__ __forceinline__ size_t woff(int g, int k){
    int ch = k >> 6;
    int u  = ((k >> 3) & 7) ^ (g & 7);
    return (((size_t)ch*GG + g)*8 + u)*8 + (k & 7);
}

__device__ __forceinline__ ull pack2(float lo, float hi){
    ull r; asm("mov.b64 %0, {%1,%2};" : "=l"(r) : "f"(lo), "f"(hi)); return r;
}
__device__ __forceinline__ void unpack2(ull v, float &lo, float &hi){
    asm("mov.b64 {%0,%1}, %2;" : "=f"(lo), "=f"(hi) : "l"(v));
}
__device__ __forceinline__ ull ffma2(ull a, ull b, ull c){
    ull d; asm("fma.rn.f32x2 %0, %1, %2, %3;" : "=l"(d) : "l"(a), "l"(b), "l"(c)); return d;
}
__device__ __forceinline__ float fsigmoid(float x){ return __fdividef(1.f, 1.f + __expf(-x)); }
__device__ __forceinline__ float ftanh(float x){
    float r; asm("tanh.approx.f32 %0, %1;" : "=f"(r) : "f"(x)); return r;
}
__device__ __forceinline__ uint smem_u32(const void* p){
    uint a; asm("{ .reg .u64 t; cvta.to.shared.u64 t, %1; cvt.u32.u64 %0, t; }" : "=r"(a) : "l"(p));
    return a;
}
__device__ __forceinline__ void bsplit(float v, __nv_bfloat16 &h, __nv_bfloat16 &l){
    h = __float2bfloat16(v);
    l = __float2bfloat16(v - __bfloat162float(h));
}
__device__ __forceinline__ void cp16(uint dst, const void* src){
    asm volatile("cp.async.cg.shared.global [%0], [%1], 16;" :: "r"(dst), "l"(src));
}
#define CP_COMMIT() asm volatile("cp.async.commit_group;" ::: "memory")
#define CP_WAIT0()  asm volatile("cp.async.wait_group 0;" ::: "memory")

#define MBAR_INIT(a) asm volatile("mbarrier.init.shared.b64 [%0], %1;" :: "r"(a), "r"(1u) : "memory")
#define MBAR_EXPECT(a, bytes) asm volatile("mbarrier.arrive.expect_tx.shared.b64 _, [%0], %1;" :: "r"(a), "r"(bytes) : "memory")
#define WAITP(a, par) do{ \
    asm volatile("{\n\t.reg .pred P;\n\tWL_%=:\n\t" \
      "mbarrier.try_wait.parity.acquire.cta.shared::cta.b64 P, [%0], %1, 0x989680;\n\t" \
      "@P bra.uni WD_%=;\n\tbra.uni WL_%=;\n\tWD_%=:\n\t}" \
      :: "r"(a), "r"(par) : "memory"); }while(0)
#define BULK_G2S(dst, src, bytes, mbar) \
    asm volatile("cp.async.bulk.shared::cluster.global.mbarrier::complete_tx::bytes [%0], [%1], %2, [%3];" \
        :: "r"(dst), "l"(src), "r"(bytes), "r"(mbar) : "memory")

__device__ __forceinline__ void mma16816(float* c, const uint* a, uint b0, uint b1){
    asm volatile("mma.sync.aligned.m16n8k16.row.col.f32.bf16.bf16.f32 "
        "{%0,%1,%2,%3}, {%4,%5,%6,%7}, {%8,%9}, {%0,%1,%2,%3};"
        : "+f"(c[0]), "+f"(c[1]), "+f"(c[2]), "+f"(c[3])
        : "r"(a[0]), "r"(a[1]), "r"(a[2]), "r"(a[3]), "r"(b0), "r"(b1));
}
#define LDM4(r, addr) \
    asm volatile("ldmatrix.sync.aligned.m8n8.x4.shared.b16 {%0,%1,%2,%3}, [%4];" \
        : "=r"((r)[0]), "=r"((r)[1]), "=r"((r)[2]), "=r"((r)[3]) : "r"(addr))

// ---------------- init ----------------
__global__ void init_kernel(const float* __restrict__ data, const float* __restrict__ masks,
                            const float* __restrict__ bhr){
    int t = blockIdx.x*blockDim.x + threadIdx.x;
    int stride = gridDim.x*blockDim.x;
    for (int idx=t; idx<BB*KPA; idx+=stride){
        int b = idx/KPA, k = idx - b*KPA;
        float v = 0.f;
        if (k < DD){
            float m = masks[(size_t)b*SS*DD + k];
            v = m*data[(size_t)b*SS*DD + k] + (1.f-m)*bhr[k];
        }
        __nv_bfloat16 h, l; bsplit(v, h, l);
        size_t o = aoff(b, k);
        g_Ah[o] = h; g_Al[o] = l;
    }
    for (size_t idx=t; idx<(size_t)SS*2*BB*64; idx+=stride){
        int e  = (int)(idx & 7);
        int u  = (int)((idx >> 3) & 7);
        int b  = (int)((idx >> 6) & (BB-1));
        int c2 = (int)((idx >> 16) & 1);
        int s  = (int)(idx >> 17);
        int uo = u ^ (b & 7);
        int d  = c2*64 + uo*8 + e;
        g_Ms[idx] = __float2bfloat16(masks[((size_t)b*SS + s)*DD + d]);
    }
    for (int i=t;i<HH*BB;i+=stride) g_c[i]=0.f;
    if (t < SS) g_loss[t]=0.f;
}

// ---------------- build ----------------
__global__ void build_kernel(const float* __restrict__ Wih, const float* __restrict__ Whh,
                             const float* __restrict__ bih, const float* __restrict__ bhh,
                             const float* __restrict__ Whr, const float* __restrict__ Wfr){
    int t0 = blockIdx.x*blockDim.x + threadIdx.x;
    int stride = gridDim.x*blockDim.x;
    const int IN = 2*DD + 1;
    for (size_t idx=t0; idx<(size_t)GG*KPW; idx+=stride){
        int gcol = (int)(idx / KPW);
        int k    = (int)(idx - (size_t)gcol*KPW);
        int j = gcol >> 2, gate = gcol & 3;
        int gs = gate*HH + j;
        float v;
        if (k < DD)           v = Wih[(size_t)gs*IN + k];
        else if (k < DD+HH)   v = Whh[(size_t)gs*HH + (k-DD)];
        else                  v = Wih[(size_t)gs*IN + DD + (k-DD-HH)];
        __nv_bfloat16 h, l; bsplit(v, h, l);
        size_t o = woff(gcol, k);
        g_Wh[o] = h; g_Wl[o] = l;
    }
    for (int gcol=t0; gcol<GG; gcol+=stride){
        int j = gcol>>2, gate = gcol&3; int gs = gate*HH + j;
        g_biasI[gcol] = bih[gs] + bhh[gs];
        g_Wd[gcol]    = Wih[(size_t)gs*IN + 2*DD];
    }
    for (int idx=t0; idx<HH*DD; idx+=stride){
        int k = idx >> 7, n = idx & (DD-1);
        g_Bc[idx] = Whr[(size_t)n*HH + k];
    }
    for (int idx=t0; idx<DD*DD; idx+=stride){
        int k = idx >> 7, n = idx & (DD-1);
        g_Bc2[idx] = Wfr[(size_t)n*DD + k];
    }
}

__global__ void msum_kernel(const float* __restrict__ masks){
    __shared__ float red[256];
    int s = blockIdx.x;
    float sum = 0.f;
    for (int idx = threadIdx.x; idx < BB*DD; idx += 256){
        int b = idx >> 7, d = idx & (DD-1);
        sum += masks[(size_t)b*SS*DD + (size_t)s*DD + d];
    }
    red[threadIdx.x] = sum; __syncthreads();
    #pragma unroll
    for (int off=128; off>0; off>>=1){
        if (threadIdx.x < off) red[threadIdx.x] += red[threadIdx.x+off];
        __syncthreads();
    }
    if (threadIdx.x == 0) g_msum[s] = red[0];
}

// ---------------- xf: precompute x@WfrT + bfr ----------------
__global__ __launch_bounds__(256,1) void xf_kernel(const float* __restrict__ data,
                                                   const float* __restrict__ bfr){
    __shared__ float xs[64][132];
    int tid = threadIdx.x;
    int r0 = blockIdx.x * 64;
    #pragma unroll
    for (int i = 0; i < 8; i++){
        int lin = i*256 + tid;
        int row = lin >> 5, q = lin & 31;
        *(float4*)&xs[row][q*4] = *(const float4*)&data[(size_t)(r0+row)*DD + q*4];
    }
    __syncthreads();
    int colq = tid & 31;
    int rowg = tid >> 5;
    float acc[8][4];
    #pragma unroll
    for (int r=0;r<8;r++){ acc[r][0]=0.f; acc[r][1]=0.f; acc[r][2]=0.f; acc[r][3]=0.f; }
    #pragma unroll 4
    for (int k = 0; k < DD; k++){
        float4 b4 = *(const float4*)&g_Bc2[k*DD + colq*4];
        #pragma unroll
        for (int r = 0; r < 8; r++){
            float xv = xs[rowg*8 + r][k];
            acc[r][0] = fmaf(xv, b4.x, acc[r][0]);
            acc[r][1] = fmaf(xv, b4.y, acc[r][1]);
            acc[r][2] = fmaf(xv, b4.z, acc[r][2]);
            acc[r][3] = fmaf(xv, b4.w, acc[r][3]);
        }
    }
    float4 bf = *(const float4*)&bfr[colq*4];
    #pragma unroll
    for (int r = 0; r < 8; r++){
        float4 o = make_float4(acc[r][0]+bf.x, acc[r][1]+bf.y, acc[r][2]+bf.z, acc[r][3]+bf.w);
        *(float4*)&g_XF[(size_t)(r0 + rowg*8 + r)*DD + colq*4] = o;
    }
}

// ---------------- gates: 64x128 CTA tile, 8 warps (32x32 each), 2 CTA/SM ----------------
__global__ __launch_bounds__(256,2) void gates_kernel(const float* __restrict__ deltas, int s){
    extern __shared__ __align__(16) char smem[];
    uint sb = smem_u32(smem);
    uint mb0 = sb + 2*BUF_B;
    uint mb1 = mb0 + 8;
    float* sh_dd = (float*)(smem + 2*BUF_B + 32);
    int tid = threadIdx.x;
    int w    = tid >> 5;
    int lane = tid & 31;
    int g  = lane >> 2;
    int t2 = lane & 3;
    int wm = w & 1;           // rows wm*32 (of 64)
    int wn = w >> 1;          // cols wn*32 (of 128)
    int row0 = blockIdx.y * 64;
    int col0 = blockIdx.x * 128;

    if (tid == 0){ MBAR_INIT(mb0); MBAR_INIT(mb1); }
    if (tid < 64) sh_dd[tid] = deltas[(size_t)(row0+tid)*SS + s];
    __syncthreads();

    int lrow = lane & 15;
    int hi   = lane >> 4;
    int sw7  = lrow & 7;
    uint baseA0 = (uint)((wm*32 +      lrow)*128);
    uint baseA1 = (uint)((wm*32 + 16 + lrow)*128);
    uint baseB0 = (uint)((wn*32 +      lrow)*128);
    uint baseB1 = (uint)((wn*32 + 16 + lrow)*128);

    float acc[32];
    #pragma unroll
    for (int i = 0; i < 32; i++) acc[i] = 0.f;

    if (tid == 0){
        MBAR_EXPECT(mb0, BUF_B);
        BULK_G2S(sb + 0,                 g_Ah + ((size_t)0*BB + row0)*64, TILE_A, mb0);
        BULK_G2S(sb + TILE_A,            g_Al + ((size_t)0*BB + row0)*64, TILE_A, mb0);
        BULK_G2S(sb + 2*TILE_A,          g_Wh + ((size_t)0*GG + col0)*64, TILE_W, mb0);
        BULK_G2S(sb + 2*TILE_A + TILE_W, g_Wl + ((size_t)0*GG + col0)*64, TILE_W, mb0);
    }

    uint ph0 = 0, ph1 = 0;
    for (int ch = 0; ch < NCH; ch++){
        int buf = ch & 1;
        uint mb = buf ? mb1 : mb0;
        if (buf){ WAITP(mb, ph1); ph1 ^= 1; }
        else    { WAITP(mb, ph0); ph0 ^= 1; }

        if (tid == 0 && ch+1 < NCH){
            int nc = ch + 1;
            int nb = nc & 1;
            uint mbn = nb ? mb1 : mb0;
            uint db = sb + nb*BUF_B;
            size_t kcW = ((size_t)nc*GG + col0)*64;
            const __nv_bfloat16* srcA = (nc < 10)
                ? g_Ah + ((size_t)nc*BB + row0)*64
                : g_Ms + ((size_t)(s*2 + (nc-10))*BB + row0)*64;
            bool needAl = (nc < 10);
            MBAR_EXPECT(mbn, needAl ? BUF_B : (BUF_B - TILE_A));
            BULK_G2S(db + 0, srcA, TILE_A, mbn);
            if (needAl) BULK_G2S(db + TILE_A, g_Al + ((size_t)nc*BB + row0)*64, TILE_A, mbn);
            BULK_G2S(db + 2*TILE_A,          g_Wh + kcW, TILE_W, mbn);
            BULK_G2S(db + 2*TILE_A + TILE_W, g_Wl + kcW, TILE_W, mbn);
        }

        uint tAh = sb + buf*BUF_B;
        uint tAl = tAh + TILE_A;
        uint tBh = tAh + 2*TILE_A;
        uint tBl = tBh + TILE_W;
        bool haveAl = (ch < 10);

        #pragma unroll
        for (int kk = 0; kk < 4; kk++){
            uint off = (uint)(((((kk<<1)|hi) ^ sw7)) << 4);
            uint ah[2][4], al[2][4], bh[2][4], bl[2][4];
            LDM4(ah[0], tAh + baseA0 + off);
            LDM4(ah[1], tAh + baseA1 + off);
            LDM4(bh[0], tBh + baseB0 + off);
            LDM4(bh[1], tBh + baseB1 + off);
            LDM4(bl[0], tBl + baseB0 + off);
            LDM4(bl[1], tBl + baseB1 + off);
            if (haveAl){
                LDM4(al[0], tAl + baseA0 + off);
                LDM4(al[1], tAl + baseA1 + off);
            }
            #pragma unroll
            for (int ma = 0; ma < 2; ma++){
                #pragma unroll
                for (int na = 0; na < 4; na++){
                    int nb = na >> 1, hf = na & 1;
                    float* c = &acc[(ma*4 + na)*4];
                    mma16816(c, ah[ma], bh[nb][hf], bh[nb][hf+2]);
                    mma16816(c, ah[ma], bl[nb][hf], bl[nb][hf+2]);
                    if (haveAl) mma16816(c, al[ma], bh[nb][hf], bh[nb][hf+2]);
                }
            }
        }
        __syncthreads();
    }

    #pragma unroll
    for (int ma = 0; ma < 2; ma++){
        float dd0 = sh_dd[wm*32 + ma*16 + g];
        float dd1 = sh_dd[wm*32 + ma*16 + g + 8];
        #pragma unroll
        for (int na = 0; na < 4; na++){
            float* c = &acc[(ma*4 + na)*4];
            int nb = col0 + wn*32 + na*8;
            int gc = nb + t2*2;
            float2 bi = *(const float2*)&g_biasI[gc];
            float2 wd = *(const float2*)&g_Wd[gc];
            c[0] += bi.x + dd0*wd.x; c[1] += bi.y + dd0*wd.y;
            c[2] += bi.x + dd1*wd.x; c[3] += bi.y + dd1*wd.y;
            float p0 = __shfl_xor_sync(0xFFFFFFFFu, c[0], 1);
            float p1 = __shfl_xor_sync(0xFFFFFFFFu, c[1], 1);
            float p2 = __shfl_xor_sync(0xFFFFFFFFu, c[2], 1);
            float p3 = __shfl_xor_sync(0xFFFFFFFFu, c[3], 1);
            int j = (nb >> 2) + (t2 >> 1);
            int row = wm*32 + ma*16 + g + ((t2 & 1) ? 8 : 0);
            float gi, gf, gg, go;
            if ((t2 & 1) == 0){ gi = c[0]; gf = c[1]; gg = p0; go = p1; }
            else              { gi = p2;   gf = p3;   gg = c[2]; go = c[3]; }
            int b = row0 + row;
            size_t o = (size_t)j*BB + b;
            float cold = g_c[o];
            float cn = fsigmoid(gf)*cold + fsigmoid(gi)*ftanh(gg);
            g_c[o] = cn;
            g_h[o] = fsigmoid(go)*ftanh(cn);
        }
    }
}

// ---------------- mid: R14 shape, K=512 ----------------
__global__ __launch_bounds__(256,1) void mid_kernel(
    const float* __restrict__ data, const float* __restrict__ masks,
    const float* __restrict__ deltas, const float* __restrict__ Wtd,
    const float* __restrict__ btd, const float* __restrict__ bhr,
    float* __restrict__ out, int s)
{
    extern __shared__ __align__(16) float smd[];
    float* sh_h  = smd + MID_H;
    float* sh_hd = smd + MID_HD;
    float* Bsb   = smd + MID_BS;
    float* red   = smd + MID_RED;
    float* sh_d  = smd + MID_D;
    int tid = threadIdx.x;
    int m0 = blockIdx.x * 8;
    int tx = tid & 31, ty = tid >> 5;
    bool hasNext = (s+1 < SS);

    int st_kk = tid >> 5;
    int st_n4 = (tid & 31) << 2;
    uint bsaddr0 = smem_u32(Bsb);
    uint bsrow  = (uint)(st_kk*132 + st_n4)*4;
    uint bsrow2 = (uint)((st_kk+8)*132 + st_n4)*4;
    #define STAGE(k0, bu) do{ \
        cp16(bsaddr0 + (bu)*16*132*4 + bsrow,  &g_Bc[(size_t)((k0)+st_kk)*DD + st_n4]); \
        cp16(bsaddr0 + (bu)*16*132*4 + bsrow2, &g_Bc[(size_t)((k0)+st_kk+8)*DD + st_n4]); \
        CP_COMMIT(); }while(0)

    STAGE(0, 0);

    if (tid < 8) sh_d[tid] = hasNext ? deltas[(size_t)(m0+tid)*SS + s + 1] : 0.f;
    __syncthreads();

    #pragma unroll 4
    for (int i = 0; i < 16; i++){
        int lin = i*256 + tid;
        int k = lin >> 3, r = lin & 7;
        float hv = g_h[(size_t)k*BB + m0 + r];
        sh_h[r*516 + k] = hv;
        float hd = 0.f;
        if (hasNext){
            float td = sh_d[r]*Wtd[k] + btd[k];
            hd = hv * __expf(-fmaxf(td, 0.f));
        }
        sh_hd[r*516 + k] = hd;
    }
    __syncthreads();

    if (hasNext){
        int r = tid >> 5, lw = tid & 31;
        int b = m0 + r;
        __align__(16) __nv_bfloat16 th[16], tl[16];
        #pragma unroll
        for (int q = 0; q < 16; q++) bsplit(sh_hd[r*516 + lw*16+q], th[q], tl[q]);
        #pragma unroll
        for (int h2 = 0; h2 < 2; h2++){
            int ug = 16 + lw*2 + h2;
            int ch = ug >> 3, u = (ug & 7) ^ (b & 7);
            size_t o = (((size_t)ch*BB + b)*8 + u)*8;
            *(uint4*)(g_Ah + o) = *(uint4*)(th + h2*8);
            *(uint4*)(g_Al + o) = *(uint4*)(tl + h2*8);
        }
    }

    ull aH[2]={0,0}, aD[2]={0,0};
    for (int k0 = 0; k0 < HH; k0 += 16){
        int buf = (k0 >> 4) & 1;
        CP_WAIT0();
        __syncthreads();
        if (k0 + 16 < HH) STAGE(k0+16, buf^1);
        const float* Bt = Bsb + buf*16*132;
        #pragma unroll
        for (int kk = 0; kk < 16; kk++){
            float4 bv = *(const float4*)&Bt[kk*132 + tx*4];
            ull b0 = pack2(bv.x, bv.y), b1 = pack2(bv.z, bv.w);
            float ah = sh_h[ty*516 + k0+kk];  ull a2 = pack2(ah, ah);
            aH[0] = ffma2(a2, b0, aH[0]); aH[1] = ffma2(a2, b1, aH[1]);
            float ad = sh_hd[ty*516 + k0+kk]; ull d2 = pack2(ad, ad);
            aD[0] = ffma2(d2, b0, aD[0]); aD[1] = ffma2(d2, b1, aD[1]);
        }
    }

    int b = m0 + ty, n0 = tx*4;
    float h2v[4], hd[4];
    unpack2(aH[0], h2v[0], h2v[1]); unpack2(aH[1], h2v[2], h2v[3]);
    unpack2(aD[0], hd[0], hd[1]);  unpack2(aD[1], hd[2], hd[3]);
    float4 brv = *(const float4*)&bhr[n0];
    size_t go = ((size_t)b*SS + s)*DD + n0;
    float4 xv  = *(const float4*)&data [go];
    float4 mv  = *(const float4*)&masks[go];
    float4 xfv = *(const float4*)&g_XF [go];
    float brr[4]={brv.x,brv.y,brv.z,brv.w};
    float xr[4]={xv.x,xv.y,xv.z,xv.w}, mr[4]={mv.x,mv.y,mv.z,mv.w};
    float xfr[4]={xfv.x,xfv.y,xfv.z,xfv.w};
    float lsum = 0.f, ov[4];
    #pragma unroll
    for (int q = 0; q < 4; q++){
        float xh2 = h2v[q] + brr[q];
        ov[q] = mr[q]*xr[q] + (1.f-mr[q])*(xh2 + xfr[q]);
        float e = xr[q] - xh2;
        lsum += e*e*mr[q];
    }
    *(float4*)&out[go] = make_float4(ov[0], ov[1], ov[2], ov[3]);

    if (hasNext){
        float4 xn = *(const float4*)&data [go + DD];
        float4 mn = *(const float4*)&masks[go + DD];
        float xnr[4]={xn.x,xn.y,xn.z,xn.w}, mnr[4]={mn.x,mn.y,mn.z,mn.w};
        __align__(8) __nv_bfloat16 ah4[4], al4[4];
        #pragma unroll
        for (int q = 0; q < 4; q++){
            float xh = hd[q] + brr[q];
            float xc = mnr[q]*xnr[q] + (1.f-mnr[q])*xh;
            bsplit(xc, ah4[q], al4[q]);
        }
        int ug = n0 >> 3;
        int ch = ug >> 3, u = (ug & 7) ^ (b & 7);
        size_t o = (((size_t)ch*BB + b)*8 + u)*8 + (n0 & 7);
        *(uint2*)(g_Ah + o) = *(uint2*)ah4;
        *(uint2*)(g_Al + o) = *(uint2*)al4;
    }

    red[tid] = lsum; __syncthreads();
    #pragma unroll
    for (int off = 128; off > 0; off >>= 1){
        if (tid < off) red[tid] += red[tid+off];
        __syncthreads();
    }
    if (tid == 0) atomicAdd(&g_loss[s], red[0]);
}

__global__ void final_kernel(float* __restrict__ out, int out_size){
    __shared__ float red[256];
    int s = threadIdx.x;
    red[s] = g_loss[s] / (g_msum[s] + 1e-5f);
    __syncthreads();
    #pragma unroll
    for (int off = 128; off > 0; off >>= 1){
        if (s < off) red[s] += red[s+off];
        __syncthreads();
    }
    if (s == 0 && out_size > NIMP) out[NIMP] = red[0] / (float)SS;
}

extern "C" void kernel_launch(void* const* d_in, const int* in_sizes, int n_in,
                              void* d_out, int out_size){
    const float* data   = (const float*)d_in[0];
    const float* masks  = (const float*)d_in[1];
    const float* deltas = (const float*)d_in[2];
    const float* Wih    = (const float*)d_in[3];
    const float* Whh    = (const float*)d_in[4];
    const float* bih    = (const float*)d_in[5];
    const float* bhh    = (const float*)d_in[6];
    const float* Wtd    = (const float*)d_in[7];
    const float* btd    = (const float*)d_in[8];
    const float* Whr    = (const float*)d_in[9];
    const float* bhr    = (const float*)d_in[10];
    const float* Wfr    = (const float*)d_in[11];
    const float* bfr    = (const float*)d_in[12];
    float* out = (float*)d_out;

    cudaFuncSetAttribute(gates_kernel, cudaFuncAttributeMaxDynamicSharedMemorySize, GATES_SMEM);
    cudaFuncSetAttribute(mid_kernel, cudaFuncAttributeMaxDynamicSharedMemorySize, MID_SMEM);

    init_kernel<<<2048, 256>>>(data, masks, bhr);
    build_kernel<<<512, 256>>>(Wih, Whh, bih, bhh, Whr, Wfr);
    msum_kernel<<<SS, 256>>>(masks);
    xf_kernel<<<(BB*SS)/64, 256>>>(data, bfr);
    for (int s = 0; s < SS; s++){
        gates_kernel<<<dim3(16, 16), 256, GATES_SMEM>>>(deltas, s);
        mid_kernel<<<BB/8, 256, MID_SMEM>>>(data, masks, deltas, Wtd, btd, bhr, out, s);
    }
    final_kernel<<<1, 256>>>(out, out_size);
}

// round 16
// speedup vs baseline: 1.0074x; 1.0074x over previous
#include <cuda_runtime.h>
#include <cuda_bf16.h>
#include <math.h>

#define BB 1024
#define SS 256
#define DD 128
#define HH 512
#define GG 2048
#define KPA 640
#define KPW 768
#define NCH 12
#define NIMP (1024*256*128)

#define TILE16K 16384
#define BUF_B (4*TILE16K)
#define GATES_SMEM (3*BUF_B + 32 + 512)

#define MID_H    0
#define MID_HD   (8*516)
#define MID_BS   (2*8*516)
#define MID_RED  (MID_BS + 2*16*132)
#define MID_D    (MID_RED + 256)
#define MID_SMEM ((MID_D + 8)*4)

typedef unsigned long long ull;
typedef unsigned int uint;

__device__ uint4 g_AhV[BB*KPA/8];
__device__ uint4 g_AlV[BB*KPA/8];
__device__ uint4 g_WhV[(size_t)GG*KPW/8];
__device__ uint4 g_WlV[(size_t)GG*KPW/8];
__device__ uint4 g_MsV[(size_t)SS*2*BB*64/8];
__device__ float g_XF[(size_t)BB*SS*DD];
__device__ float g_h[HH*BB];
__device__ float g_c[HH*BB];
__device__ float g_Bc[HH*DD];
__device__ float g_Bc2[DD*DD];
__device__ float g_biasI[GG];
__device__ float g_Wd[GG];
__device__ float g_loss[SS];
__device__ float g_msum[SS];

#define g_Ah ((__nv_bfloat16*)g_AhV)
#define g_Al ((__nv_bfloat16*)g_AlV)
#define g_Wh ((__nv_bfloat16*)g_WhV)
#define g_Wl ((__nv_bfloat16*)g_WlV)
#define g_Ms ((__nv_bfloat16*)g_MsV)

__device__ __forceinline__ size_t aoff(int b, int k){
    int ch = k >> 6;
    int u  = ((k >> 3) & 7) ^ (b & 7);
    return (((size_t)ch*BB + b)*8 + u)*8 + (k & 7);
}
__device__ __forceinline__ size_t woff(int g, int k){
    int ch = k >> 6;
    int u  = ((k >> 3) & 7) ^ (g & 7);
    return (((size_t)ch*GG + g)*8 + u)*8 + (k & 7);
}

__device__ __forceinline__ ull pack2(float lo, float hi){
    ull r; asm("mov.b64 %0, {%1,%2};" : "=l"(r) : "f"(lo), "f"(hi)); return r;
}
__device__ __forceinline__ void unpack2(ull v, float &lo, float &hi){
    asm("mov.b64 {%0,%1}, %2;" : "=f"(lo), "=f"(hi) : "l"(v));
}
__device__ __forceinline__ ull ffma2(ull a, ull b, ull c){
    ull d; asm("fma.rn.f32x2 %0, %1, %2, %3;" : "=l"(d) : "l"(a), "l"(b), "l"(c)); return d;
}
__device__ __forceinline__ float fsigmoid(float x){ return __fdividef(1.f, 1.f + __expf(-x)); }
__device__ __forceinline__ float ftanh(float x){
    float r; asm("tanh.approx.f32 %0, %1;" : "=f"(r) : "f"(x)); return r;
}
__device__ __forceinline__ uint smem_u32(const void* p){
    uint a; asm("{ .reg .u64 t; cvta.to.shared.u64 t, %1; cvt.u32.u64 %0, t; }" : "=r"(a) : "l"(p));
    return a;
}
__device__ __forceinline__ void bsplit(float v, __nv_bfloat16 &h, __nv_bfloat16 &l){
    h = __float2bfloat16(v);
    l = __float2bfloat16(v - __bfloat162float(h));
}
__device__ __forceinline__ void cp16(uint dst, const void* src){
    asm volatile("cp.async.cg.shared.global [%0], [%1], 16;" :: "r"(dst), "l"(src));
}
#define CP_COMMIT() asm volatile("cp.async.commit_group;" ::: "memory")
#define CP_WAIT0()  asm volatile("cp.async.wait_group 0;" ::: "memory")

#define MBAR_INIT(a) asm volatile("mbarrier.init.shared.b64 [%0], %1;" :: "r"(a), "r"(1u) : "memory")
#define MBAR_EXPECT(a, bytes) asm volatile("mbarrier.arrive.expect_tx.shared.b64 _, [%0], %1;" :: "r"(a), "r"(bytes) : "memory")
#define WAITP(a, par) do{ \
    asm volatile("{\n\t.reg .pred P;\n\tWL_%=:\n\t" \
      "mbarrier.try_wait.parity.acquire.cta.shared::cta.b64 P, [%0], %1, 0x989680;\n\t" \
      "@P bra.uni WD_%=;\n\tbra.uni WL_%=;\n\tWD_%=:\n\t}" \
      :: "r"(a), "r"(par) : "memory"); }while(0)
#define BULK_G2S(dst, src, bytes, mbar) \
    asm volatile("cp.async.bulk.shared::cluster.global.mbarrier::complete_tx::bytes [%0], [%1], %2, [%3];" \
        :: "r"(dst), "l"(src), "r"(bytes), "r"(mbar) : "memory")

__device__ __forceinline__ void mma16816(float* c, const uint* a, uint b0, uint b1){
    asm volatile("mma.sync.aligned.m16n8k16.row.col.f32.bf16.bf16.f32 "
        "{%0,%1,%2,%3}, {%4,%5,%6,%7}, {%8,%9}, {%0,%1,%2,%3};"
        : "+f"(c[0]), "+f"(c[1]), "+f"(c[2]), "+f"(c[3])
        : "r"(a[0]), "r"(a[1]), "r"(a[2]), "r"(a[3]), "r"(b0), "r"(b1));
}
#define LDM4(r, addr) \
    asm volatile("ldmatrix.sync.aligned.m8n8.x4.shared.b16 {%0,%1,%2,%3}, [%4];" \
        : "=r"((r)[0]), "=r"((r)[1]), "=r"((r)[2]), "=r"((r)[3]) : "r"(addr))

__global__ void init_kernel(const float* __restrict__ data, const float* __restrict__ masks,
                            const float* __restrict__ bhr){
    int t = blockIdx.x*blockDim.x + threadIdx.x;
    int stride = gridDim.x*blockDim.x;
    for (int idx=t; idx<BB*KPA; idx+=stride){
        int b = idx/KPA, k = idx - b*KPA;
        float v = 0.f;
        if (k < DD){
            float m = masks[(size_t)b*SS*DD + k];
            v = m*data[(size_t)b*SS*DD + k] + (1.f-m)*bhr[k];
        }
        __nv_bfloat16 h, l; bsplit(v, h, l);
        size_t o = aoff(b, k);
        g_Ah[o] = h; g_Al[o] = l;
    }
    for (size_t idx=t; idx<(size_t)SS*2*BB*64; idx+=stride){
        int e  = (int)(idx & 7);
        int u  = (int)((idx >> 3) & 7);
        int b  = (int)((idx >> 6) & (BB-1));
        int c2 = (int)((idx >> 16) & 1);
        int s  = (int)(idx >> 17);
        int uo = u ^ (b & 7);
        int d  = c2*64 + uo*8 + e;
        g_Ms[idx] = __float2bfloat16(masks[((size_t)b*SS + s)*DD + d]);
    }
    for (int i=t;i<HH*BB;i+=stride) g_c[i]=0.f;
    if (t < SS) g_loss[t]=0.f;
}

__global__ void build_kernel(const float* __restrict__ Wih, const float* __restrict__ Whh,
                             const float* __restrict__ bih, const float* __restrict__ bhh,
                             const float* __restrict__ Whr, const float* __restrict__ Wfr){
    int t0 = blockIdx.x*blockDim.x + threadIdx.x;
    int stride = gridDim.x*blockDim.x;
    const int IN = 2*DD + 1;
    for (size_t idx=t0; idx<(size_t)GG*KPW; idx+=stride){
        int gcol = (int)(idx / KPW);
        int k    = (int)(idx - (size_t)gcol*KPW);
        int j = gcol >> 2, gate = gcol & 3;
        int gs = gate*HH + j;
        float v;
        if (k < DD)           v = Wih[(size_t)gs*IN + k];
        else if (k < DD+HH)   v = Whh[(size_t)gs*HH + (k-DD)];
        else                  v = Wih[(size_t)gs*IN + DD + (k-DD-HH)];
        __nv_bfloat16 h, l; bsplit(v, h, l);
        size_t o = woff(gcol, k);
        g_Wh[o] = h; g_Wl[o] = l;
    }
    for (int gcol=t0; gcol<GG; gcol+=stride){
        int j = gcol>>2, gate = gcol&3; int gs = gate*HH + j;
        g_biasI[gcol] = bih[gs] + bhh[gs];
        g_Wd[gcol]    = Wih[(size_t)gs*IN + 2*DD];
    }
    for (int idx=t0; idx<HH*DD; idx+=stride){
        int k = idx >> 7, n = idx & (DD-1);
        g_Bc[idx] = Whr[(size_t)n*HH + k];
    }
    for (int idx=t0; idx<DD*DD; idx+=stride){
        int k = idx >> 7, n = idx & (DD-1);
        g_Bc2[idx] = Wfr[(size_t)n*DD + k];
    }
}

__global__ void msum_kernel(const float* __restrict__ masks){
    __shared__ float red[256];
    int s = blockIdx.x;
    float sum = 0.f;
    for (int idx = threadIdx.x; idx < BB*DD; idx += 256){
        int b = idx >> 7, d = idx & (DD-1);
        sum += masks[(size_t)b*SS*DD + (size_t)s*DD + d];
    }
    red[threadIdx.x] = sum; __syncthreads();
    #pragma unroll
    for (int off=128; off>0; off>>=1){
        if (threadIdx.x < off) red[threadIdx.x] += red[threadIdx.x+off];
        __syncthreads();
    }
    if (threadIdx.x == 0) g_msum[s] = red[0];
}

__global__ __launch_bounds__(256,1) void xf_kernel(const float* __restrict__ data,
                                                   const float* __restrict__ bfr){
    __shared__ float xs[64][132];
    int tid = threadIdx.x;
    int r0 = blockIdx.x * 64;
    #pragma unroll
    for (int i = 0; i < 8; i++){
        int lin = i*256 + tid;
        int row = lin >> 5, q = lin & 31;
        *(float4*)&xs[row][q*4] = *(const float4*)&data[(size_t)(r0+row)*DD + q*4];
    }
    __syncthreads();
    int colq = tid & 31;
    int rowg = tid >> 5;
    float acc[8][4];
    #pragma unroll
    for (int r=0;r<8;r++){ acc[r][0]=0.f; acc[r][1]=0.f; acc[r][2]=0.f; acc[r][3]=0.f; }
    #pragma unroll 4
    for (int k = 0; k < DD; k++){
        float4 b4 = *(const float4*)&g_Bc2[k*DD + colq*4];
        #pragma unroll
        for (int r = 0; r < 8; r++){
            float xv = xs[rowg*8 + r][k];
            acc[r][0] = fmaf(xv, b4.x, acc[r][0]);
            acc[r][1] = fmaf(xv, b4.y, acc[r][1]);
            acc[r][2] = fmaf(xv, b4.z, acc[r][2]);
            acc[r][3] = fmaf(xv, b4.w, acc[r][3]);
        }
    }
    float4 bf = *(const float4*)&bfr[colq*4];
    #pragma unroll
    for (int r = 0; r < 8; r++){
        float4 o = make_float4(acc[r][0]+bf.x, acc[r][1]+bf.y, acc[r][2]+bf.z, acc[r][3]+bf.w);
        *(float4*)&g_XF[(size_t)(r0 + rowg*8 + r)*DD + colq*4] = o;
    }
}

// ---------------- gates: R12 shape + 3-stage copy ring ----------------
__device__ __forceinline__ void issue_gchunk(uint db, uint mbn, int nc, int row0, int col0, int s){
    size_t kcW = ((size_t)nc*GG + col0)*64;
    const __nv_bfloat16* srcA = (nc < 10)
        ? g_Ah + ((size_t)nc*BB + row0)*64
        : g_Ms + ((size_t)(s*2 + (nc-10))*BB + row0)*64;
    bool needAl = (nc < 10);
    MBAR_EXPECT(mbn, needAl ? 4*TILE16K : 3*TILE16K);
    BULK_G2S(db + 0*TILE16K, srcA, TILE16K, mbn);
    if (needAl) BULK_G2S(db + 1*TILE16K, g_Al + ((size_t)nc*BB + row0)*64, TILE16K, mbn);
    BULK_G2S(db + 2*TILE16K, g_Wh + kcW, TILE16K, mbn);
    BULK_G2S(db + 3*TILE16K, g_Wl + kcW, TILE16K, mbn);
}

__global__ __launch_bounds__(512,1) void gates_kernel(const float* __restrict__ deltas, int s){
    extern __shared__ __align__(16) char smem[];
    uint sb = smem_u32(smem);
    uint mbB = sb + 3*BUF_B;
    float* sh_dd = (float*)(smem + 3*BUF_B + 32);
    int tid = threadIdx.x;
    int w    = tid >> 5;
    int lane = tid & 31;
    int g  = lane >> 2;
    int t2 = lane & 3;
    int wm = w & 3;
    int wn = w >> 2;
    int row0 = blockIdx.y * 128;
    int col0 = blockIdx.x * 128;

    if (tid == 0){ MBAR_INIT(mbB); MBAR_INIT(mbB+8); MBAR_INIT(mbB+16); }
    if (tid < 128) sh_dd[tid] = deltas[(size_t)(row0+tid)*SS + s];
    __syncthreads();

    int lrow = lane & 15;
    int hi   = lane >> 4;
    int sw7  = lrow & 7;
    uint baseA0 = (uint)((wm*32 +      lrow)*128);
    uint baseA1 = (uint)((wm*32 + 16 + lrow)*128);
    uint baseB0 = (uint)((wn*32 +      lrow)*128);
    uint baseB1 = (uint)((wn*32 + 16 + lrow)*128);

    float acc[32];
    #pragma unroll
    for (int i = 0; i < 32; i++) acc[i] = 0.f;

    if (tid == 0){
        issue_gchunk(sb + 0*BUF_B, mbB + 0,  0, row0, col0, s);
        issue_gchunk(sb + 1*BUF_B, mbB + 8,  1, row0, col0, s);
        issue_gchunk(sb + 2*BUF_B, mbB + 16, 2, row0, col0, s);
    }

    uint ph0 = 0, ph1 = 0, ph2 = 0;
    int buf = 0;
    for (int ch = 0; ch < NCH; ch++){
        uint mb = mbB + buf*8;
        if      (buf == 0){ WAITP(mb, ph0); ph0 ^= 1; }
        else if (buf == 1){ WAITP(mb, ph1); ph1 ^= 1; }
        else              { WAITP(mb, ph2); ph2 ^= 1; }

        uint tAh = sb + buf*BUF_B;
        uint tAl = tAh + TILE16K;
        uint tBh = tAh + 2*TILE16K;
        uint tBl = tAh + 3*TILE16K;
        bool haveAl = (ch < 10);

        #pragma unroll
        for (int kk = 0; kk < 4; kk++){
            uint off = (uint)(((((kk<<1)|hi) ^ sw7)) << 4);
            uint ah[2][4], al[2][4], bh[2][4], bl[2][4];
            LDM4(ah[0], tAh + baseA0 + off);
            LDM4(ah[1], tAh + baseA1 + off);
            LDM4(bh[0], tBh + baseB0 + off);
            LDM4(bh[1], tBh + baseB1 + off);
            LDM4(bl[0], tBl + baseB0 + off);
            LDM4(bl[1], tBl + baseB1 + off);
            if (haveAl){
                LDM4(al[0], tAl + baseA0 + off);
                LDM4(al[1], tAl + baseA1 + off);
            }
            #pragma unroll
            for (int ma = 0; ma < 2; ma++){
                #pragma unroll
                for (int na = 0; na < 4; na++){
                    int nb = na >> 1, hf = na & 1;
                    float* c = &acc[(ma*4 + na)*4];
                    mma16816(c, ah[ma], bh[nb][hf], bh[nb][hf+2]);
                    mma16816(c, ah[ma], bl[nb][hf], bl[nb][hf+2]);
                    if (haveAl) mma16816(c, al[ma], bh[nb][hf], bh[nb][hf+2]);
                }
            }
        }
        __syncthreads();
        if (tid == 0 && ch + 3 < NCH){
            issue_gchunk(sb + buf*BUF_B, mbB + buf*8, ch + 3, row0, col0, s);
        }
        buf = (buf == 2) ? 0 : buf + 1;
    }

    #pragma unroll
    for (int ma = 0; ma < 2; ma++){
        float dd0 = sh_dd[wm*32 + ma*16 + g];
        float dd1 = sh_dd[wm*32 + ma*16 + g + 8];
        #pragma unroll
        for (int na = 0; na < 4; na++){
            float* c = &acc[(ma*4 + na)*4];
            int nb = col0 + wn*32 + na*8;
            int gc = nb + t2*2;
            float2 bi = *(const float2*)&g_biasI[gc];
            float2 wd = *(const float2*)&g_Wd[gc];
            c[0] += bi.x + dd0*wd.x; c[1] += bi.y + dd0*wd.y;
            c[2] += bi.x + dd1*wd.x; c[3] += bi.y + dd1*wd.y;
            float p0 = __shfl_xor_sync(0xFFFFFFFFu, c[0], 1);
            float p1 = __shfl_xor_sync(0xFFFFFFFFu, c[1], 1);
            float p2 = __shfl_xor_sync(0xFFFFFFFFu, c[2], 1);
            float p3 = __shfl_xor_sync(0xFFFFFFFFu, c[3], 1);
            int j = (nb >> 2) + (t2 >> 1);
            int row = wm*32 + ma*16 + g + ((t2 & 1) ? 8 : 0);
            float gi, gf, gg, go;
            if ((t2 & 1) == 0){ gi = c[0]; gf = c[1]; gg = p0; go = p1; }
            else              { gi = p2;   gf = p3;   gg = c[2]; go = c[3]; }
            int b = row0 + row;
            size_t o = (size_t)j*BB + b;
            float cold = g_c[o];
            float cn = fsigmoid(gf)*cold + fsigmoid(gi)*ftanh(gg);
            g_c[o] = cn;
            g_h[o] = fsigmoid(go)*ftanh(cn);
        }
    }
}

// ---------------- mid: R14 shape, K=512 ----------------
__global__ __launch_bounds__(256,1) void mid_kernel(
    const float* __restrict__ data, const float* __restrict__ masks,
    const float* __restrict__ deltas, const float* __restrict__ Wtd,
    const float* __restrict__ btd, const float* __restrict__ bhr,
    float* __restrict__ out, int s)
{
    extern __shared__ __align__(16) float smd[];
    float* sh_h  = smd + MID_H;
    float* sh_hd = smd + MID_HD;
    float* Bsb   = smd + MID_BS;
    float* red   = smd + MID_RED;
    float* sh_d  = smd + MID_D;
    int tid = threadIdx.x;
    int m0 = blockIdx.x * 8;
    int tx = tid & 31, ty = tid >> 5;
    bool hasNext = (s+1 < SS);

    int st_kk = tid >> 5;
    int st_n4 = (tid & 31) << 2;
    uint bsaddr0 = smem_u32(Bsb);
    uint bsrow  = (uint)(st_kk*132 + st_n4)*4;
    uint bsrow2 = (uint)((st_kk+8)*132 + st_n4)*4;
    #define STAGE(k0, bu) do{ \
        cp16(bsaddr0 + (bu)*16*132*4 + bsrow,  &g_Bc[(size_t)((k0)+st_kk)*DD + st_n4]); \
        cp16(bsaddr0 + (bu)*16*132*4 + bsrow2, &g_Bc[(size_t)((k0)+st_kk+8)*DD + st_n4]); \
        CP_COMMIT(); }while(0)

    STAGE(0, 0);

    if (tid < 8) sh_d[tid] = hasNext ? deltas[(size_t)(m0+tid)*SS + s + 1] : 0.f;
    __syncthreads();

    #pragma unroll 4
    for (int i = 0; i < 16; i++){
        int lin = i*256 + tid;
        int k = lin >> 3, r = lin & 7;
        float hv = g_h[(size_t)k*BB + m0 + r];
        sh_h[r*516 + k] = hv;
        float hd = 0.f;
        if (hasNext){
            float td = sh_d[r]*Wtd[k] + btd[k];
            hd = hv * __expf(-fmaxf(td, 0.f));
        }
        sh_hd[r*516 + k] = hd;
    }
    __syncthreads();

    if (hasNext){
        int r = tid >> 5, lw = tid & 31;
        int b = m0 + r;
        __align__(16) __nv_bfloat16 th[16], tl[16];
        #pragma unroll
        for (int q = 0; q < 16; q++) bsplit(sh_hd[r*516 + lw*16+q], th[q], tl[q]);
        #pragma unroll
        for (int h2 = 0; h2 < 2; h2++){
            int ug = 16 + lw*2 + h2;
            int ch = ug >> 3, u = (ug & 7) ^ (b & 7);
            size_t o = (((size_t)ch*BB + b)*8 + u)*8;
            *(uint4*)(g_Ah + o) = *(uint4*)(th + h2*8);
            *(uint4*)(g_Al + o) = *(uint4*)(tl + h2*8);
        }
    }

    ull aH[2]={0,0}, aD[2]={0,0};
    for (int k0 = 0; k0 < HH; k0 += 16){
        int buf = (k0 >> 4) & 1;
        CP_WAIT0();
        __syncthreads();
        if (k0 + 16 < HH) STAGE(k0+16, buf^1);
        const float* Bt = Bsb + buf*16*132;
        #pragma unroll
        for (int kk = 0; kk < 16; kk++){
            float4 bv = *(const float4*)&Bt[kk*132 + tx*4];
            ull b0 = pack2(bv.x, bv.y), b1 = pack2(bv.z, bv.w);
            float ah = sh_h[ty*516 + k0+kk];  ull a2 = pack2(ah, ah);
            aH[0] = ffma2(a2, b0, aH[0]); aH[1] = ffma2(a2, b1, aH[1]);
            float ad = sh_hd[ty*516 + k0+kk]; ull d2 = pack2(ad, ad);
            aD[0] = ffma2(d2, b0, aD[0]); aD[1] = ffma2(d2, b1, aD[1]);
        }
    }

    int b = m0 + ty, n0 = tx*4;
    float h2v[4], hd[4];
    unpack2(aH[0], h2v[0], h2v[1]); unpack2(aH[1], h2v[2], h2v[3]);
    unpack2(aD[0], hd[0], hd[1]);  unpack2(aD[1], hd[2], hd[3]);
    float4 brv = *(const float4*)&bhr[n0];
    size_t go = ((size_t)b*SS + s)*DD + n0;
    float4 xv  = *(const float4*)&data [go];
    float4 mv  = *(const float4*)&masks[go];
    float4 xfv = *(const float4*)&g_XF [go];
    float brr[4]={brv.x,brv.y,brv.z,brv.w};
    float xr[4]={xv.x,xv.y,xv.z,xv.w}, mr[4]={mv.x,mv.y,mv.z,mv.w};
    float xfr[4]={xfv.x,xfv.y,xfv.z,xfv.w};
    float lsum = 0.f, ov[4];
    #pragma unroll
    for (int q = 0; q < 4; q++){
        float xh2 = h2v[q] + brr[q];
        ov[q] = mr[q]*xr[q] + (1.f-mr[q])*(xh2 + xfr[q]);
        float e = xr[q] - xh2;
        lsum += e*e*mr[q];
    }
    *(float4*)&out[go] = make_float4(ov[0], ov[1], ov[2], ov[3]);

    if (hasNext){
        float4 xn = *(const float4*)&data [go + DD];
        float4 mn = *(const float4*)&masks[go + DD];
        float xnr[4]={xn.x,xn.y,xn.z,xn.w}, mnr[4]={mn.x,mn.y,mn.z,mn.w};
        __align__(8) __nv_bfloat16 ah4[4], al4[4];
        #pragma unroll
        for (int q = 0; q < 4; q++){
            float xh = hd[q] + brr[q];
            float xc = mnr[q]*xnr[q] + (1.f-mnr[q])*xh;
            bsplit(xc, ah4[q], al4[q]);
        }
        int ug = n0 >> 3;
        int ch = ug >> 3, u = (ug & 7) ^ (b & 7);
        size_t o = (((size_t)ch*BB + b)*8 + u)*8 + (n0 & 7);
        *(uint2*)(g_Ah + o) = *(uint2*)ah4;
        *(uint2*)(g_Al + o) = *(uint2*)al4;
    }

    red[tid] = lsum; __syncthreads();
    #pragma unroll
    for (int off = 128; off > 0; off >>= 1){
        if (tid < off) red[tid] += red[tid+off];
        __syncthreads();
    }
    if (tid == 0) atomicAdd(&g_loss[s], red[0]);
}

__global__ void final_kernel(float* __restrict__ out, int out_size){
    __shared__ float red[256];
    int s = threadIdx.x;
    red[s] = g_loss[s] / (g_msum[s] + 1e-5f);
    __syncthreads();
    #pragma unroll
    for (int off = 128; off > 0; off >>= 1){
        if (s < off) red[s] += red[s+off];
        __syncthreads();
    }
    if (s == 0 && out_size > NIMP) out[NIMP] = red[0] / (float)SS;
}

extern "C" void kernel_launch(void* const* d_in, const int* in_sizes, int n_in,
                              void* d_out, int out_size){
    const float* data   = (const float*)d_in[0];
    const float* masks  = (const float*)d_in[1];
    const float* deltas = (const float*)d_in[2];
    const float* Wih    = (const float*)d_in[3];
    const float* Whh    = (const float*)d_in[4];
    const float* bih    = (const float*)d_in[5];
    const float* bhh    = (const float*)d_in[6];
    const float* Wtd    = (const float*)d_in[7];
    const float* btd    = (const float*)d_in[8];
    const float* Whr    = (const float*)d_in[9];
    const float* bhr    = (const float*)d_in[10];
    const float* Wfr    = (const float*)d_in[11];
    const float* bfr    = (const float*)d_in[12];
    float* out = (float*)d_out;

    cudaFuncSetAttribute(gates_kernel, cudaFuncAttributeMaxDynamicSharedMemorySize, GATES_SMEM);
    cudaFuncSetAttribute(mid_kernel, cudaFuncAttributeMaxDynamicSharedMemorySize, MID_SMEM);

    init_kernel<<<2048, 256>>>(data, masks, bhr);
    build_kernel<<<512, 256>>>(Wih, Whh, bih, bhh, Whr, Wfr);
    msum_kernel<<<SS, 256>>>(masks);
    xf_kernel<<<(BB*SS)/64, 256>>>(data, bfr);
    for (int s = 0; s < SS; s++){
        gates_kernel<<<dim3(16, 8), 512, GATES_SMEM>>>(deltas, s);
        mid_kernel<<<BB/8, 256, MID_SMEM>>>(data, masks, deltas, Wtd, btd, bhr, out, s);
    }
    final_kernel<<<1, 256>>>(out, out_size);
}